// round 5
// baseline (speedup 1.0000x reference)
#include <cuda_runtime.h>
#include <cuda_bf16.h>

// 10-qubit, batch-16384 circuit: RY embedding + 2x StronglyEntanglingLayers.
// R3: (R2 + fixed device-constexpr qualifiers). CNOTs eliminated via GF(2)
// basis relabeling, embedding+layer0 folded into product-state tree, complex
// math packed f32x2. One sample per warp; 1024 amps = 16 f32x2 re + 16 f32x2
// im regs per lane. Stored index s = lane*32 + k, k = 2p + h (h = pack half).

#define N_QUBITS 10
#define BATCH    16384

using ull = unsigned long long;

// ---------------- constexpr GF(2) relabeling ----------------
struct M10 { unsigned r[10]; };  // r[b] = mask of stored bits whose parity = phys bit b

__host__ __device__ constexpr M10 mident() {
    M10 m{}; for (int b = 0; b < 10; b++) m.r[b] = 1u << b; return m;
}

// Apply CNOT ring (ctrl wire q -> tgt wire (q+rr)%10, q=0..9 sequential): M <- C*M
__host__ __device__ constexpr M10 mring(M10 m, int rr) {
    for (int q = 0; q < 10; q++) {
        int t = (q + rr) % 10;
        m.r[9 - t] ^= m.r[9 - q];   // wire w <-> bit 9-w
    }
    return m;
}

__host__ __device__ constexpr M10 minv(M10 a) {
    M10 inv = mident();
    for (int col = 0; col < 10; col++) {
        int piv = col;
        while (!((a.r[piv] >> col) & 1)) piv++;
        unsigned t = a.r[col]; a.r[col] = a.r[piv]; a.r[piv] = t;
        t = inv.r[col]; inv.r[col] = inv.r[piv]; inv.r[piv] = t;
        for (int r2 = 0; r2 < 10; r2++)
            if (r2 != col && ((a.r[r2] >> col) & 1)) { a.r[r2] ^= a.r[col]; inv.r[r2] ^= inv.r[col]; }
    }
    return inv;
}

__host__ __device__ constexpr unsigned mcol(M10 n, int b) {
    unsigned w = 0;
    for (int sb = 0; sb < 10; sb++) if ((n.r[sb] >> b) & 1) w |= 1u << sb;
    return w;
}

__host__ __device__ constexpr unsigned hibit(unsigned x) {
    unsigned b = 1; while (x >> 1) { x >>= 1; b <<= 1; } return b;
}

constexpr M10 kM1 = mring(mident(), 1);  // after layer-0 CNOT ring (r=1)
constexpr M10 kN1 = minv(kM1);
constexpr M10 kM2 = mring(kM1, 2);       // after layer-1 CNOT ring (r=2)

// ---------------- packed f32x2 primitives ----------------
__device__ __forceinline__ ull pk2(float lo, float hi) {
    ull u; asm("mov.b64 %0, {%1, %2};" : "=l"(u) : "f"(lo), "f"(hi)); return u;
}
__device__ __forceinline__ void un2(ull u, float& a, float& b) {
    asm("mov.b64 {%0, %1}, %2;" : "=f"(a), "=f"(b) : "l"(u));
}
__device__ __forceinline__ ull fma2(ull a, ull b, ull c) {
    ull d; asm("fma.rn.f32x2 %0, %1, %2, %3;" : "=l"(d) : "l"(a), "l"(b), "l"(c)); return d;
}
__device__ __forceinline__ ull mul2(ull a, ull b) {
    ull d; asm("mul.rn.f32x2 %0, %1, %2;" : "=l"(d) : "l"(a), "l"(b)); return d;
}
__device__ __forceinline__ ull add2(ull a, ull b) {
    ull d; asm("add.rn.f32x2 %0, %1, %2;" : "=l"(d) : "l"(a), "l"(b)); return d;
}
__device__ __forceinline__ ull shfl64x(ull v, int m) {
    float a, b; un2(v, a, b);
    a = __shfl_xor_sync(0xFFFFFFFFu, a, m);
    b = __shfl_xor_sync(0xFFFFFFFFu, b, m);
    return pk2(a, b);
}
__device__ __forceinline__ ull swap2(ull v) {
    float a, b; un2(v, a, b); return pk2(b, a);
}

// ---------------- precomputed Rot matrices ----------------
__device__ float2 g_rot[2 * N_QUBITS * 4];  // [l][q][4]: m00,m01,m10,m11

__global__ void precompute_rot_kernel(const float* __restrict__ qw) {
    int i = threadIdx.x;
    if (i < 2 * N_QUBITS) {
        float phi = qw[i * 3 + 0], theta = qw[i * 3 + 1], omega = qw[i * 3 + 2];
        float st, ct;   sincosf(0.5f * theta, &st, &ct);
        float spo, cpo; sincosf(0.5f * (phi + omega), &spo, &cpo);
        float smo, cmo; sincosf(0.5f * (phi - omega), &smo, &cmo);
        g_rot[i * 4 + 0] = make_float2(cpo * ct, -spo * ct);   // m00
        g_rot[i * 4 + 1] = make_float2(-cmo * st, -smo * st);  // m01
        g_rot[i * 4 + 2] = make_float2(cmo * st, -smo * st);   // m10
        g_rot[i * 4 + 3] = make_float2(cpo * ct, spo * ct);    // m11
    }
}

// ---------------- generalized single-qubit gate ----------------
// Pairs stored s with s^W; role (|0>/|1> side) = parity(s & R).
template <unsigned W, unsigned R>
__device__ __forceinline__ void gate(ull* rr, ull* ii, int lane,
                                     float2 m00, float2 m01, float2 m10, float2 m11) {
    constexpr unsigned wl = W & 31u;
    constexpr unsigned wh = (W >> 5) & 31u;
    constexpr unsigned rl = R & 31u;
    constexpr unsigned rh = (R >> 5) & 31u;
    constexpr unsigned pw = wl >> 1;          // pack-index xor for partner
    constexpr unsigned pr = rl >> 1;          // pack-index role-parity mask
    constexpr bool xh  = (wl & 1u) != 0;      // partner crosses pack halves
    constexpr bool rhd = (rl & 1u) != 0;      // role differs between halves

    const unsigned lane_par = (0x96696996u >> (lane & rh)) & 1u;

    // Coef packs: A used where parity(p & pr)==0 (role_lo = lane_par),
    //             B where parity==1 (role_lo = lane_par^1). role_hi = role_lo^rhd.
    ull Ao_re, Ao_im, Ao_imn, At_re, At_im, At_imn;
    ull Bo_re, Bo_im, Bo_imn, Bt_re, Bt_im, Bt_imn;
    {
        const unsigned r0 = lane_par, r0h = r0 ^ (rhd ? 1u : 0u);
        const unsigned r1 = r0 ^ 1u,  r1h = r1 ^ (rhd ? 1u : 0u);
        float2 aol = r0 ? m11 : m00, aoh = r0h ? m11 : m00;
        float2 atl = r0 ? m10 : m01, ath = r0h ? m10 : m01;
        Ao_re = pk2(aol.x, aoh.x); Ao_im = pk2(aol.y, aoh.y); Ao_imn = pk2(-aol.y, -aoh.y);
        At_re = pk2(atl.x, ath.x); At_im = pk2(atl.y, ath.y); At_imn = pk2(-atl.y, -ath.y);
        float2 bol = r1 ? m11 : m00, boh = r1h ? m11 : m00;
        float2 btl = r1 ? m10 : m01, bth = r1h ? m10 : m01;
        Bo_re = pk2(bol.x, boh.x); Bo_im = pk2(bol.y, boh.y); Bo_imn = pk2(-bol.y, -boh.y);
        Bt_re = pk2(btl.x, bth.x); Bt_im = pk2(btl.y, bth.y); Bt_imn = pk2(-btl.y, -bth.y);
    }

#define CUPD(nre, nim, are, aie, ore, oie, CB)                                            \
    {                                                                                     \
        ull cwre = (CB) ? Bo_re : Ao_re, cwim = (CB) ? Bo_im : Ao_im,                     \
            cwmn = (CB) ? Bo_imn : Ao_imn;                                                \
        ull ctre = (CB) ? Bt_re : At_re, ctim = (CB) ? Bt_im : At_im,                     \
            ctmn = (CB) ? Bt_imn : At_imn;                                                \
        (nre) = fma2(cwre, (are), fma2(cwmn, (aie), fma2(ctre, (ore), mul2(ctmn, (oie))))); \
        (nim) = fma2(cwre, (aie), fma2(cwim, (are), fma2(ctre, (oie), mul2(ctim, (ore))))); \
    }

    if constexpr (pw == 0) {
        // partner pack == own pack (via lane xor and/or half swap)
#pragma unroll
        for (int p = 0; p < 16; p++) {
            ull ore = rr[p], oie = ii[p];
            if constexpr (wh != 0) { ore = shfl64x(ore, (int)wh); oie = shfl64x(oie, (int)wh); }
            if constexpr (xh)      { ore = swap2(ore); oie = swap2(oie); }
            const bool cB = ((0x6996u >> (p & pr)) & 1u) != 0;
            ull nre, nim;
            CUPD(nre, nim, rr[p], ii[p], ore, oie, cB);
            rr[p] = nre; ii[p] = nim;
        }
    } else {
        constexpr unsigned selbit = hibit(pw);
#pragma unroll
        for (int p = 0; p < 16; p++) {
            if (p & (int)selbit) continue;  // canonical element of each pair
            const int p2 = p ^ (int)pw;
            ull oa_re = rr[p2], oa_ie = ii[p2];  // "other" for p
            ull ob_re = rr[p],  ob_ie = ii[p];   // "other" for p2
            if constexpr (wh != 0) {
                oa_re = shfl64x(oa_re, (int)wh); oa_ie = shfl64x(oa_ie, (int)wh);
                ob_re = shfl64x(ob_re, (int)wh); ob_ie = shfl64x(ob_ie, (int)wh);
            }
            if constexpr (xh) {
                oa_re = swap2(oa_re); oa_ie = swap2(oa_ie);
                ob_re = swap2(ob_re); ob_ie = swap2(ob_ie);
            }
            const bool cA = ((0x6996u >> (p  & pr)) & 1u) != 0;
            const bool cC = ((0x6996u >> (p2 & pr)) & 1u) != 0;
            ull nre1, nim1, nre2, nim2;
            CUPD(nre1, nim1, rr[p],  ii[p],  oa_re, oa_ie, cA);
            CUPD(nre2, nim2, rr[p2], ii[p2], ob_re, ob_ie, cC);
            rr[p] = nre1; ii[p] = nim1; rr[p2] = nre2; ii[p2] = nim2;
        }
    }
#undef CUPD
}

// Layer-1 Rot on wire Q in relabeled basis (W from N1 column, role from M1 row).
template <int Q>
__device__ __forceinline__ void apply_l1(ull* rr, ull* ii, int lane) {
    constexpr int b = 9 - Q;
    constexpr unsigned W = mcol(kN1, b);
    constexpr unsigned R = kM1.r[b];
    const float2* m = &g_rot[(N_QUBITS + Q) * 4];
    float2 m00 = __ldg(&m[0]), m01 = __ldg(&m[1]), m10 = __ldg(&m[2]), m11 = __ldg(&m[3]);
    gate<W, R>(rr, ii, lane, m00, m01, m10, m11);
}

// <Z_wireQ> partial sum for this lane: sign = parity(s & row_{9-Q}(M2)).
template <int Q>
__device__ __forceinline__ float expz(const ull* pp, int lane, ull neg1) {
    constexpr unsigned mr = kM2.r[9 - Q];
    constexpr unsigned rl = mr & 31u;
    constexpr unsigned rh = (mr >> 5) & 31u;
    constexpr unsigned pr = rl >> 1;
    ull acc = pp[0];  // p=0: parity 0 -> +
#pragma unroll
    for (int p = 1; p < 16; p++) {
        if (((0x6996u >> (p & pr)) & 1u) != 0) acc = fma2(pp[p], neg1, acc);
        else                                   acc = add2(acc, pp[p]);
    }
    float a, b; un2(acc, a, b);
    float z = (rl & 1u) ? (a - b) : (a + b);
    if ((0x96696996u >> (lane & rh)) & 1u) z = -z;
    return z;
}

// ---------------- main kernel ----------------
__global__ void __launch_bounds__(256)
sim_kernel(const float* __restrict__ x, float* __restrict__ out) {
    const int warp = (blockIdx.x * blockDim.x + threadIdx.x) >> 5;
    const int lane = threadIdx.x & 31;
    if (warp >= BATCH) return;

    // Per-wire factors after RY(x_q) then Rot(l=0,q): (f0,f1) = M_rot * (cos, sin)
    float2 f0[10], f1[10];
    {
        const float* xs = x + warp * N_QUBITS;
#pragma unroll
        for (int q = 0; q < 10; q++) {
            float s, c; sincosf(0.5f * __ldg(&xs[q]), &s, &c);
            const float2* m = &g_rot[q * 4];
            float2 m00 = __ldg(&m[0]), m01 = __ldg(&m[1]), m10 = __ldg(&m[2]), m11 = __ldg(&m[3]);
            f0[q] = make_float2(fmaf(m01.x, s, m00.x * c), fmaf(m01.y, s, m00.y * c));
            f1[q] = make_float2(fmaf(m11.x, s, m10.x * c), fmaf(m11.y, s, m10.y * c));
        }
    }

    // Lane factor: lane bit j <-> stored bit 5+j <-> wire 4-j
    float2 lf = (lane & 1) ? f1[4] : f0[4];
#pragma unroll
    for (int j = 1; j < 5; j++) {
        float2 g = ((lane >> j) & 1) ? f1[4 - j] : f0[4 - j];
        lf = make_float2(lf.x * g.x - lf.y * g.y, lf.x * g.y + lf.y * g.x);
    }

    // Local product tree: k bit j <-> wire 9-j; pack half = k bit0 (wire 9)
    ull rr[16], ii[16];
    {
        float2 a0 = make_float2(f0[9].x * lf.x - f0[9].y * lf.y, f0[9].x * lf.y + f0[9].y * lf.x);
        float2 a1 = make_float2(f1[9].x * lf.x - f1[9].y * lf.y, f1[9].x * lf.y + f1[9].y * lf.x);
        rr[0] = pk2(a0.x, a1.x); ii[0] = pk2(a0.y, a1.y);
    }
#pragma unroll
    for (int j = 1; j < 5; j++) {
        const int n = 1 << (j - 1);
        float2 w0 = f0[9 - j], w1 = f1[9 - j];
        ull w0re = pk2(w0.x, w0.x), w0im = pk2(w0.y, w0.y), w0mn = pk2(-w0.y, -w0.y);
        ull w1re = pk2(w1.x, w1.x), w1im = pk2(w1.y, w1.y), w1mn = pk2(-w1.y, -w1.y);
#pragma unroll
        for (int p = 0; p < n; p++) {
            ull zr = rr[p], zi = ii[p];
            rr[p | n] = fma2(w1re, zr, mul2(w1mn, zi));
            ii[p | n] = fma2(w1re, zi, mul2(w1im, zr));
            rr[p]     = fma2(w0re, zr, mul2(w0mn, zi));
            ii[p]     = fma2(w0re, zi, mul2(w0im, zr));
        }
    }
    // State now == (embedding + layer0 Rots); layer0 CNOT ring absorbed into masks.

    // Layer-1 Rot gates in relabeled basis
    apply_l1<0>(rr, ii, lane);
    apply_l1<1>(rr, ii, lane);
    apply_l1<2>(rr, ii, lane);
    apply_l1<3>(rr, ii, lane);
    apply_l1<4>(rr, ii, lane);
    apply_l1<5>(rr, ii, lane);
    apply_l1<6>(rr, ii, lane);
    apply_l1<7>(rr, ii, lane);
    apply_l1<8>(rr, ii, lane);
    apply_l1<9>(rr, ii, lane);
    // Layer-1 CNOT ring absorbed into measurement masks (M2).

    // Probabilities (packed) and expectation values
    ull pp[16];
#pragma unroll
    for (int p = 0; p < 16; p++) pp[p] = fma2(rr[p], rr[p], mul2(ii[p], ii[p]));

    const ull neg1 = pk2(-1.0f, -1.0f);
    float zv[10];
    zv[0] = expz<0>(pp, lane, neg1);
    zv[1] = expz<1>(pp, lane, neg1);
    zv[2] = expz<2>(pp, lane, neg1);
    zv[3] = expz<3>(pp, lane, neg1);
    zv[4] = expz<4>(pp, lane, neg1);
    zv[5] = expz<5>(pp, lane, neg1);
    zv[6] = expz<6>(pp, lane, neg1);
    zv[7] = expz<7>(pp, lane, neg1);
    zv[8] = expz<8>(pp, lane, neg1);
    zv[9] = expz<9>(pp, lane, neg1);

#pragma unroll
    for (int off = 16; off > 0; off >>= 1) {
#pragma unroll
        for (int q = 0; q < 10; q++)
            zv[q] += __shfl_xor_sync(0xFFFFFFFFu, zv[q], off);
    }

    if (lane == 0) {
        float* o = out + warp * N_QUBITS;
#pragma unroll
        for (int q = 0; q < N_QUBITS; q++) o[q] = zv[q];
    }
}

extern "C" void kernel_launch(void* const* d_in, const int* in_sizes, int n_in,
                              void* d_out, int out_size) {
    const float* x  = (const float*)d_in[0];  // [16384, 10]
    const float* qw = (const float*)d_in[1];  // [2, 10, 3]
    float* out = (float*)d_out;               // [16384, 10]

    precompute_rot_kernel<<<1, 32>>>(qw);

    const int threads = 256;
    const int blocks  = (BATCH * 32) / threads;
    sim_kernel<<<blocks, threads>>>(x, out);
}

// round 7
// speedup vs baseline: 1.0673x; 1.0673x over previous
#include <cuda_runtime.h>
#include <cuda_bf16.h>

// 10-qubit, batch-16384 circuit: RY embedding + 2x StronglyEntanglingLayers.
// R7 = R6 with kM2 epilogue access moved behind a template (compile-time only).
// Compact 4-scalar Rot coefficients, WHT epilogue, folded prologue, 3 blk/SM.
// CNOTs eliminated via GF(2) relabeling; packed f32x2 complex math.

#define N_QUBITS 10
#define BATCH    16384

using ull = unsigned long long;

// ---------------- constexpr GF(2) relabeling ----------------
struct M10 { unsigned r[10]; };

__host__ __device__ constexpr M10 mident() {
    M10 m{}; for (int b = 0; b < 10; b++) m.r[b] = 1u << b; return m;
}
__host__ __device__ constexpr M10 mring(M10 m, int rr) {
    for (int q = 0; q < 10; q++) {
        int t = (q + rr) % 10;
        m.r[9 - t] ^= m.r[9 - q];
    }
    return m;
}
__host__ __device__ constexpr M10 minv(M10 a) {
    M10 inv = mident();
    for (int col = 0; col < 10; col++) {
        int piv = col;
        while (!((a.r[piv] >> col) & 1)) piv++;
        unsigned t = a.r[col]; a.r[col] = a.r[piv]; a.r[piv] = t;
        t = inv.r[col]; inv.r[col] = inv.r[piv]; inv.r[piv] = t;
        for (int r2 = 0; r2 < 10; r2++)
            if (r2 != col && ((a.r[r2] >> col) & 1)) { a.r[r2] ^= a.r[col]; inv.r[r2] ^= inv.r[col]; }
    }
    return inv;
}
__host__ __device__ constexpr unsigned mcol(M10 n, int b) {
    unsigned w = 0;
    for (int sb = 0; sb < 10; sb++) if ((n.r[sb] >> b) & 1) w |= 1u << sb;
    return w;
}
__host__ __device__ constexpr unsigned hibit(unsigned x) {
    unsigned b = 1; while (x >> 1) { x >>= 1; b <<= 1; } return b;
}

constexpr M10 kM1 = mring(mident(), 1);
constexpr M10 kN1 = minv(kM1);
constexpr M10 kM2 = mring(kM1, 2);

// ---------------- packed f32x2 primitives ----------------
__device__ __forceinline__ ull pk2(float lo, float hi) {
    ull u; asm("mov.b64 %0, {%1, %2};" : "=l"(u) : "f"(lo), "f"(hi)); return u;
}
__device__ __forceinline__ void un2(ull u, float& a, float& b) {
    asm("mov.b64 {%0, %1}, %2;" : "=f"(a), "=f"(b) : "l"(u));
}
__device__ __forceinline__ ull fma2(ull a, ull b, ull c) {
    ull d; asm("fma.rn.f32x2 %0, %1, %2, %3;" : "=l"(d) : "l"(a), "l"(b), "l"(c)); return d;
}
__device__ __forceinline__ ull mul2(ull a, ull b) {
    ull d; asm("mul.rn.f32x2 %0, %1, %2;" : "=l"(d) : "l"(a), "l"(b)); return d;
}
__device__ __forceinline__ ull add2(ull a, ull b) {
    ull d; asm("add.rn.f32x2 %0, %1, %2;" : "=l"(d) : "l"(a), "l"(b)); return d;
}
__device__ __forceinline__ ull shfl64x(ull v, int m) {
    float a, b; un2(v, a, b);
    a = __shfl_xor_sync(0xFFFFFFFFu, a, m);
    b = __shfl_xor_sync(0xFFFFFFFFu, b, m);
    return pk2(a, b);
}
__device__ __forceinline__ ull swap2(ull v) {
    float a, b; un2(v, a, b); return pk2(b, a);
}

// ---------------- precomputed compact Rot coefficients ----------------
// Rot = [[P - iQ, -R - iS], [R - iS, P + iQ]] with
// P=cos((phi+omega)/2)cos(th/2), Q=sin((phi+omega)/2)cos(th/2),
// R=cos((phi-omega)/2)sin(th/2), S=sin((phi-omega)/2)sin(th/2).
__device__ float4 g_rotc[2 * N_QUBITS];

__global__ void precompute_rot_kernel(const float* __restrict__ qw) {
    int i = threadIdx.x;
    if (i < 2 * N_QUBITS) {
        float phi = qw[i * 3 + 0], theta = qw[i * 3 + 1], omega = qw[i * 3 + 2];
        float st, ct;   sincosf(0.5f * theta, &st, &ct);
        float spo, cpo; sincosf(0.5f * (phi + omega), &spo, &cpo);
        float smo, cmo; sincosf(0.5f * (phi - omega), &smo, &cmo);
        g_rotc[i] = make_float4(cpo * ct, spo * ct, cmo * st, smo * st);
    }
}

// ---------------- generalized single-qubit gate ----------------
// Pairs stored s with s^W; role parity(s & R) selects matrix row.
// Update with sigma = +1 (role0) / -1 (role1):
//   re' = P*ar + S*oi + sigma*(Q*ai - R*or)
//   im' = P*ai - S*or + sigma*(-Q*ar - R*oi)
template <unsigned W, unsigned R>
__device__ __forceinline__ void gate(ull* rr, ull* ii, int lane, float4 m) {
    constexpr unsigned wl = W & 31u;
    constexpr unsigned wh = (W >> 5) & 31u;
    constexpr unsigned rl = R & 31u;
    constexpr unsigned rh = (R >> 5) & 31u;
    constexpr unsigned pw = wl >> 1;
    constexpr unsigned pr = rl >> 1;
    constexpr bool xh  = (wl & 1u) != 0;
    constexpr bool rhd = (rl & 1u) != 0;

    const unsigned lane_par = (0x96696996u >> (lane & rh)) & 1u;
    const float sp = lane_par ? -1.0f : 1.0f;      // sigma for half-lo, parity0
    const float sh = rhd ? -sp : sp;               // sigma for half-hi, parity0

    const ull P2  = pk2(m.x, m.x);
    const ull Sv2 = pk2(m.w, m.w);
    const ull nS2 = pk2(-m.w, -m.w);
    const ull QA  = pk2(sp * m.y, sh * m.y);
    const ull nQA = pk2(-sp * m.y, -sh * m.y);
    const ull RA  = pk2(sp * m.z, sh * m.z);
    const ull nRA = pk2(-sp * m.z, -sh * m.z);

#define CUPD(nre, nim, are, aie, ore, oie, PAR)                       \
    {                                                                 \
        ull Qp_ = (PAR) ? nQA : QA;                                   \
        ull Qm_ = (PAR) ? QA : nQA;                                   \
        ull Rp_ = (PAR) ? RA : nRA;                                   \
        ull t1_ = fma2(Qp_, (aie), mul2(Rp_, (ore)));                 \
        ull t2_ = fma2(Qm_, (are), mul2(Rp_, (oie)));                 \
        (nre) = fma2(P2, (are), fma2(Sv2, (oie), t1_));               \
        (nim) = fma2(P2, (aie), fma2(nS2, (ore), t2_));               \
    }

    if constexpr (pw == 0) {
#pragma unroll
        for (int p = 0; p < 16; p++) {
            ull ore = rr[p], oie = ii[p];
            if constexpr (wh != 0) { ore = shfl64x(ore, (int)wh); oie = shfl64x(oie, (int)wh); }
            if constexpr (xh)      { ore = swap2(ore); oie = swap2(oie); }
            const bool PAR = ((0x6996u >> (p & pr)) & 1u) != 0;
            ull nre, nim;
            CUPD(nre, nim, rr[p], ii[p], ore, oie, PAR);
            rr[p] = nre; ii[p] = nim;
        }
    } else {
        constexpr unsigned selbit = hibit(pw);
#pragma unroll
        for (int p = 0; p < 16; p++) {
            if (p & (int)selbit) continue;
            const int p2 = p ^ (int)pw;
            ull oa_re = rr[p2], oa_ie = ii[p2];
            ull ob_re = rr[p],  ob_ie = ii[p];
            if constexpr (wh != 0) {
                oa_re = shfl64x(oa_re, (int)wh); oa_ie = shfl64x(oa_ie, (int)wh);
                ob_re = shfl64x(ob_re, (int)wh); ob_ie = shfl64x(ob_ie, (int)wh);
            }
            if constexpr (xh) {
                oa_re = swap2(oa_re); oa_ie = swap2(oa_ie);
                ob_re = swap2(ob_re); ob_ie = swap2(ob_ie);
            }
            const bool pA = ((0x6996u >> (p  & pr)) & 1u) != 0;
            const bool pC = ((0x6996u >> (p2 & pr)) & 1u) != 0;
            ull nre1, nim1, nre2, nim2;
            CUPD(nre1, nim1, rr[p],  ii[p],  oa_re, oa_ie, pA);
            CUPD(nre2, nim2, rr[p2], ii[p2], ob_re, ob_ie, pC);
            rr[p] = nre1; ii[p] = nim1; rr[p2] = nre2; ii[p2] = nim2;
        }
    }
#undef CUPD
}

template <int Q>
__device__ __forceinline__ void apply_l1(ull* rr, ull* ii, int lane) {
    constexpr int b = 9 - Q;
    constexpr unsigned W = mcol(kN1, b);
    constexpr unsigned R = kM1.r[b];
    float4 m = __ldg(&g_rotc[N_QUBITS + Q]);
    gate<W, R>(rr, ii, lane, m);
}

// <Z_wireQ> from WHT array (compile-time mask extraction; kM2 not ODR-used).
template <int Q>
__device__ __forceinline__ float expz_wht(const ull* pp, int lane) {
    constexpr unsigned mr = kM2.r[9 - Q];
    constexpr unsigned rl = mr & 31u;
    constexpr unsigned rh = (mr >> 5) & 31u;
    constexpr unsigned ps = rl >> 1;
    float a, b; un2(pp[ps], a, b);
    float z = (rl & 1u) ? (a - b) : (a + b);
    if ((0x96696996u >> (lane & rh)) & 1u) z = -z;
    return z;
}

__device__ __forceinline__ float2 cmul(float2 a, float2 b) {
    return make_float2(a.x * b.x - a.y * b.y, a.x * b.y + a.y * b.x);
}

// ---------------- main kernel ----------------
__global__ void __launch_bounds__(256, 3)
sim_kernel(const float* __restrict__ x, float* __restrict__ out) {
    const int warp = (blockIdx.x * blockDim.x + threadIdx.x) >> 5;
    const int lane = threadIdx.x & 31;
    if (warp >= BATCH) return;

    const float* xs = x + warp * N_QUBITS;

    // ---- Prologue: per-wire factors after RY(x_q) then Rot(l=0,q) ----
    // f0 = (P c - R s, -(Q c + S s)); f1 = (R c + P s, Q s - S c)
    // Wires 0..4 are lane bits (lane bit j <-> wire 4-j): fold immediately.
    float2 lf = make_float2(1.0f, 0.0f);
#pragma unroll
    for (int j = 0; j < 5; j++) {
        const int q = 4 - j;
        float s, c; sincosf(0.5f * __ldg(&xs[q]), &s, &c);
        float4 m = __ldg(&g_rotc[q]);
        float2 f;
        if ((lane >> j) & 1)
            f = make_float2(fmaf(m.z, c, m.x * s), fmaf(m.y, s, -m.w * c));
        else
            f = make_float2(fmaf(m.x, c, -m.z * s), -fmaf(m.y, c, m.w * s));
        lf = cmul(lf, f);
    }

    // Wires 5..9 are local bits (stored bit j <-> wire 9-j; pack half = wire 9).
    float2 f0[5], f1[5];  // index j: wire 9-j
#pragma unroll
    for (int j = 0; j < 5; j++) {
        const int q = 9 - j;
        float s, c; sincosf(0.5f * __ldg(&xs[q]), &s, &c);
        float4 m = __ldg(&g_rotc[q]);
        f0[j] = make_float2(fmaf(m.x, c, -m.z * s), -fmaf(m.y, c, m.w * s));
        f1[j] = make_float2(fmaf(m.z, c, m.x * s), fmaf(m.y, s, -m.w * c));
    }

    // Local product tree over pack-half (wire 9) and p bits (wires 8..5).
    ull rr[16], ii[16];
    {
        float2 a0 = cmul(f0[0], lf);
        float2 a1 = cmul(f1[0], lf);
        rr[0] = pk2(a0.x, a1.x); ii[0] = pk2(a0.y, a1.y);
    }
#pragma unroll
    for (int j = 1; j < 5; j++) {
        const int n = 1 << (j - 1);
        float2 w0 = f0[j], w1 = f1[j];
        ull w0re = pk2(w0.x, w0.x), w0im = pk2(w0.y, w0.y), w0mn = pk2(-w0.y, -w0.y);
        ull w1re = pk2(w1.x, w1.x), w1im = pk2(w1.y, w1.y), w1mn = pk2(-w1.y, -w1.y);
#pragma unroll
        for (int p = 0; p < n; p++) {
            ull zr = rr[p], zi = ii[p];
            rr[p | n] = fma2(w1re, zr, mul2(w1mn, zi));
            ii[p | n] = fma2(w1re, zi, mul2(w1im, zr));
            rr[p]     = fma2(w0re, zr, mul2(w0mn, zi));
            ii[p]     = fma2(w0re, zi, mul2(w0im, zr));
        }
    }
    // State == embedding + layer0 Rots; layer0 CNOT ring absorbed into masks.

    // ---- Layer-1 Rot gates in relabeled basis ----
    apply_l1<0>(rr, ii, lane);
    apply_l1<1>(rr, ii, lane);
    apply_l1<2>(rr, ii, lane);
    apply_l1<3>(rr, ii, lane);
    apply_l1<4>(rr, ii, lane);
    apply_l1<5>(rr, ii, lane);
    apply_l1<6>(rr, ii, lane);
    apply_l1<7>(rr, ii, lane);
    apply_l1<8>(rr, ii, lane);
    apply_l1<9>(rr, ii, lane);
    // Layer-1 CNOT ring absorbed into measurement masks (kM2).

    // ---- Probabilities + Walsh-Hadamard over the 4 p-bits ----
    ull pp[16];
#pragma unroll
    for (int p = 0; p < 16; p++) pp[p] = fma2(rr[p], rr[p], mul2(ii[p], ii[p]));

    const ull kNeg1 = pk2(-1.0f, -1.0f);
#pragma unroll
    for (int b = 1; b < 16; b <<= 1) {
#pragma unroll
        for (int p = 0; p < 16; p++) {
            if (p & b) continue;
            ull u = pp[p], v = pp[p | b];
            pp[p]     = add2(u, v);
            pp[p | b] = fma2(v, kNeg1, u);  // u - v
        }
    }
    // pp[mask] = sum_p (-1)^{parity(p & mask)} |amp|^2 (packed per half)

    float zv[10];
    zv[0] = expz_wht<0>(pp, lane);
    zv[1] = expz_wht<1>(pp, lane);
    zv[2] = expz_wht<2>(pp, lane);
    zv[3] = expz_wht<3>(pp, lane);
    zv[4] = expz_wht<4>(pp, lane);
    zv[5] = expz_wht<5>(pp, lane);
    zv[6] = expz_wht<6>(pp, lane);
    zv[7] = expz_wht<7>(pp, lane);
    zv[8] = expz_wht<8>(pp, lane);
    zv[9] = expz_wht<9>(pp, lane);

#pragma unroll
    for (int off = 16; off > 0; off >>= 1) {
#pragma unroll
        for (int q = 0; q < 10; q++)
            zv[q] += __shfl_xor_sync(0xFFFFFFFFu, zv[q], off);
    }

    if (lane == 0) {
        float* o = out + warp * N_QUBITS;
#pragma unroll
        for (int q = 0; q < N_QUBITS; q++) o[q] = zv[q];
    }
}

extern "C" void kernel_launch(void* const* d_in, const int* in_sizes, int n_in,
                              void* d_out, int out_size) {
    const float* x  = (const float*)d_in[0];  // [16384, 10]
    const float* qw = (const float*)d_in[1];  // [2, 10, 3]
    float* out = (float*)d_out;               // [16384, 10]

    precompute_rot_kernel<<<1, 32>>>(qw);

    const int threads = 256;
    const int blocks  = (BATCH * 32) / threads;
    sim_kernel<<<blocks, threads>>>(x, out);
}